// round 3
// baseline (speedup 1.0000x reference)
#include <cuda_runtime.h>

#define EPS 1e-8f
#define BN 4
#define CN 128
#define HN 256
#define WN 256
#define HW (HN*WN)       // 65536
#define NCH (BN*CN)      // 512
#define MHW (128*128)    // 16384
#define NPART 4

// Scratch: per-channel partial sums (NPART parts) + final coefficients.
__device__ float g_sums[NPART * NCH * 12];
__device__ float g_coef[NCH * 4];       // per channel: P, Q, k1, k2

__device__ __forceinline__ float warpSum(float v) {
#pragma unroll
    for (int o = 16; o; o >>= 1) v += __shfl_xor_sync(0xffffffffu, v, o);
    return v;
}

// ---------------------------------------------------------------------------
// Kernel 1: per-(b,c) partial reductions over a quarter of HW.
// grid = NPART * NCH (part-major). Accumulates, per tensor/region:
//   A = sum x*m, B = sum x*m^3, C = sum x^2*m^4
// Two float4-pairs batched per loop iteration for MLP; streaming loads.
// ---------------------------------------------------------------------------
__global__ __launch_bounds__(256) void k_reduce(const float4* __restrict__ x1,
                                                const float4* __restrict__ x2,
                                                const float* __restrict__ mask) {
    int ch   = blockIdx.x & (NCH - 1);
    int part = blockIdx.x >> 9;
    int b  = ch >> 7;
    const float4* p1 = x1 + (size_t)ch * (HW / 4) + part * 4096;
    const float4* p2 = x2 + (size_t)ch * (HW / 4) + part * 4096;
    const float*  mb = mask + b * MHW;
    int t = threadIdx.x;
    int qbase = part * 4096;

    float acc[12];
#pragma unroll
    for (int i = 0; i < 12; i++) acc[i] = 0.f;

#pragma unroll 1
    for (int k = 0; k < 16; k += 2) {
        int qa = t + k * 256;
        int qb = qa + 256;
        // batch all global loads up front (4x LDG.128 + 2x LDG.64)
        float4 v1a = __ldcs(p1 + qa);
        float4 v2a = __ldcs(p2 + qa);
        float4 v1b = __ldcs(p1 + qb);
        float4 v2b = __ldcs(p2 + qb);
        int qga = qbase + qa, qgb = qbase + qb;
        int ma_i = ((qga >> 7) << 7) | ((2 * qga) & 126);
        int mb_i = ((qgb >> 7) << 7) | ((2 * qgb) & 126);
        float2 mpa = *reinterpret_cast<const float2*>(mb + ma_i);
        float2 mpb = *reinterpret_cast<const float2*>(mb + mb_i);

#pragma unroll
        for (int half = 0; half < 2; half++) {
            float4 v1 = half ? v1b : v1a;
            float4 v2 = half ? v2b : v2a;
            float2 mp = half ? mpb : mpa;
            float mv[4]  = {mp.x, mp.x, mp.y, mp.y};
            float xv1[4] = {v1.x, v1.y, v1.z, v1.w};
            float xv2[4] = {v2.x, v2.y, v2.z, v2.w};
#pragma unroll
            for (int i = 0; i < 4; i++) {
                float m = mv[i], om = 1.0f - m;
                float mm = m * m, omm = om * om;
                float x = xv1[i];
                acc[0] += x * m;   float tt = x * mm;  acc[1] += tt * m;  acc[2] += tt * tt;
                acc[3] += x * om;  float t2 = x * omm; acc[4] += t2 * om; acc[5] += t2 * t2;
                x = xv2[i];
                acc[6] += x * m;   tt = x * mm;        acc[7] += tt * m;  acc[8] += tt * tt;
                acc[9] += x * om;  t2 = x * omm;       acc[10] += t2 * om; acc[11] += t2 * t2;
            }
        }
    }

    __shared__ float red[12][8];
    int lane = t & 31, wid = t >> 5;
#pragma unroll
    for (int i = 0; i < 12; i++) {
        float s = warpSum(acc[i]);
        if (lane == 0) red[i][wid] = s;
    }
    __syncthreads();
    if (wid == 0) {
#pragma unroll
        for (int i = 0; i < 12; i++) {
            float s = (lane < 8) ? red[i][lane] : 0.f;
            s = warpSum(s);
            if (lane == 0) g_sums[(size_t)(part * NCH + ch) * 12 + i] = s;
        }
    }
}

// ---------------------------------------------------------------------------
// Kernel 2 (fused): one block per batch.
// Phase A: mask sums (exact: 2x2 repeat upsample => Sum m = 4*Sum mask,
//          Sum m^2 = 4*Sum mask^2).
// Phase B: combine partial sums, per-channel mean/var -> smem.
// Phase C: 4 modulation GEMVs (coalesced, warp-per-row).
// Phase D: final per-channel coefficients:
//          out = x1*(m^2*P + om^2*Q) + k1*m + k2*om
// ---------------------------------------------------------------------------
__global__ __launch_bounds__(256) void k_final(const float* __restrict__ mask,
                                               const float* __restrict__ w_in_mean,
                                               const float* __restrict__ w_in_var,
                                               const float* __restrict__ w_out_mean,
                                               const float* __restrict__ w_out_var) {
    int b = blockIdx.x;
    int t = threadIdx.x;
    int lane = t & 31, wid = t >> 5;

    __shared__ float sred[2][8];
    __shared__ float ssum[CN * 12];
    __shared__ float v_sh[4 * 256];      // GEMV input vectors per matrix
    __shared__ float mr_sh[512];         // mu_in, r_in, mu_out, r_out
    __shared__ float ada_sh[512];        // [mat*128 + c]
    __shared__ float sh_nin, sh_nout, sh_M2, sh_M2o;

    // Phase A: mask sums
    const float* mb = mask + b * MHW;
    float s1 = 0, s2 = 0;
    for (int i = t; i < MHW; i += 256) { float m = mb[i]; s1 += m; s2 += m * m; }
    s1 = warpSum(s1); s2 = warpSum(s2);
    if (lane == 0) { sred[0][wid] = s1; sred[1][wid] = s2; }

    // Phase B1: combine the NPART partial sums
    for (int id = t; id < CN * 12; id += 256) {
        int c = id / 12, i = id - c * 12;
        float v = 0.f;
#pragma unroll
        for (int p = 0; p < NPART; p++)
            v += g_sums[(size_t)(p * NCH + b * CN + c) * 12 + i];
        ssum[id] = v;
    }
    __syncthreads();

    if (t == 0) {
        float S1 = 0, S2 = 0;
        for (int i = 0; i < 8; i++) { S1 += sred[0][i]; S2 += sred[1][i]; }
        float msum = 4.f * S1, m2sum = 4.f * S2;
        sh_nin  = msum + EPS;
        sh_nout = ((float)HW - msum) + EPS;
        sh_M2   = m2sum;
        sh_M2o  = (float)HW - 2.f * msum + m2sum;   // Sum (1-m)^2
    }
    __syncthreads();

    // Phase B2: per-channel stats
    {
        int c = t & 127;
        int isx2 = t >> 7;                 // t<128: x1 stats; t>=128: x2 stats
        const float* s = ssum + c * 12 + isx2 * 6;
        float A = s[0], Bb = s[1], Cc = s[2], Ao = s[3], Bo = s[4], Co = s[5];
        float mean_in = A / sh_nin;
        float var_in = (Cc - 2.f * mean_in * Bb + mean_in * mean_in * sh_M2) / sh_nin;
        var_in = fmaxf(var_in, 0.f);
        float mean_out = Ao / sh_nout;
        float var_out = (Co - 2.f * mean_out * Bo + mean_out * mean_out * sh_M2o) / sh_nout;
        var_out = fmaxf(var_out, 0.f);
        int vi = isx2 * 128 + c;
        v_sh[vi]       = mean_in;
        v_sh[256 + vi] = var_in;
        v_sh[512 + vi] = mean_out;
        v_sh[768 + vi] = var_out;
        if (!isx2) {
            mr_sh[c]       = mean_in;
            mr_sh[128 + c] = rsqrtf(var_in + EPS);
            mr_sh[256 + c] = mean_out;
            mr_sh[384 + c] = rsqrtf(var_out + EPS);
        }
    }
    __syncthreads();

    // Phase C: GEMVs. 512 tasks (mat*128+row), 8 warps x 64 tasks, lane along j.
    {
        const float* wmats[4] = {w_in_mean, w_in_var, w_out_mean, w_out_var};
#pragma unroll 1
        for (int it = 0; it < 64; it++) {
            int task = wid * 64 + it;
            int mat = task >> 7, row = task & 127;
            const float* wrow = wmats[mat] + (size_t)row * 256;
            const float* vv = v_sh + mat * 256;
            float a = 0.f;
#pragma unroll
            for (int j = 0; j < 8; j++)
                a = fmaf(__ldg(wrow + lane + 32 * j), vv[lane + 32 * j], a);
            a = warpSum(a);
            if (lane == 0) ada_sh[task] = a;
        }
    }
    __syncthreads();

    // Phase D: coefficients
    if (t < CN) {
        int c = t;
        float mu_i = mr_sh[c], r_i = mr_sh[128 + c];
        float mu_o = mr_sh[256 + c], r_o = mr_sh[384 + c];
        float P  = r_i * ada_sh[128 + c];          // in_var
        float Q  = r_o * ada_sh[384 + c];          // out_var
        float k1 = ada_sh[c]       - mu_i * P;     // in_mean
        float k2 = ada_sh[256 + c] - mu_o * Q;     // out_mean
        reinterpret_cast<float4*>(g_coef)[b * CN + c] = make_float4(P, Q, k1, k2);
    }
}

// ---------------------------------------------------------------------------
// Kernel 3: elementwise apply, 2 float4 per thread, streaming ld/st.
// out = x1*(m^2*P + om^2*Q) + k1*m + k2*om
// ---------------------------------------------------------------------------
__global__ __launch_bounds__(256) void k_apply(const float4* __restrict__ x1,
                                               const float* __restrict__ mask,
                                               float4* __restrict__ out) {
    int ch = blockIdx.y;
    int b = ch >> 7;
    float4 coef = __ldg(&reinterpret_cast<const float4*>(g_coef)[ch]);
    float P = coef.x, Q = coef.y, k1 = coef.z, k2 = coef.w;
    const float* mb = mask + b * MHW;
    const float4* px = x1 + (size_t)ch * (HW / 4);
    float4* po = out + (size_t)ch * (HW / 4);
    int q0 = blockIdx.x * 512 + threadIdx.x;

#pragma unroll
    for (int r = 0; r < 2; r++) {
        int q = q0 + r * 256;
        float4 v = __ldcs(px + q);
        int midx = ((q >> 7) << 7) | ((2 * q) & 126);
        float2 mp = *reinterpret_cast<const float2*>(mb + midx);
        float xs[4] = {v.x, v.y, v.z, v.w};
        float ms[4] = {mp.x, mp.x, mp.y, mp.y};
        float os[4];
#pragma unroll
        for (int i = 0; i < 4; i++) {
            float m = ms[i], om = 1.f - m;
            float s = m * m * P + om * om * Q;
            os[i] = xs[i] * s + k1 * m + k2 * om;
        }
        __stcs(po + q, make_float4(os[0], os[1], os[2], os[3]));
    }
}

extern "C" void kernel_launch(void* const* d_in, const int* in_sizes, int n_in,
                              void* d_out, int out_size) {
    const float* x1         = (const float*)d_in[0];
    const float* x2         = (const float*)d_in[1];
    const float* mask       = (const float*)d_in[2];
    const float* w_in_mean  = (const float*)d_in[3];
    const float* w_in_var   = (const float*)d_in[4];
    const float* w_out_mean = (const float*)d_in[5];
    const float* w_out_var  = (const float*)d_in[6];
    float* out = (float*)d_out;

    k_reduce<<<NPART * NCH, 256>>>((const float4*)x1, (const float4*)x2, mask);
    k_final<<<BN, 256>>>(mask, w_in_mean, w_in_var, w_out_mean, w_out_var);
    k_apply<<<dim3(HW / 4 / 512, NCH), 256>>>((const float4*)x1, mask, (float4*)out);
}